// round 10
// baseline (speedup 1.0000x reference)
#include <cuda_runtime.h>
#include <cuda_fp16.h>
#include <cstdint>

// ---------------------------------------------------------------------------
// MultiHeadAttention: B=4, L=2048, D=512, H=8, DK=DV=64
// R10 = R8 (best: 486.2us) +
//   (1) scores_kernel __launch_bounds__(256,2)  (2 CTAs/SM, was 1)
//   (2) pv: wait->sync->issue order, ONE barrier per iteration
// ---------------------------------------------------------------------------

#define DEV static __device__ __forceinline__

constexpr int Bb = 4, Ll = 2048, Dd = 512, Hh = 8;
constexpr int BL = Bb * Ll;   // 8192
constexpr int BH = Bb * Hh;   // 32
constexpr float INV_TEMP = 0.125f;   // 1/sqrt(64)
constexpr float LN_EPS = 1e-5f;

// ------------------------- scratch (static device mem) ---------------------
__device__ __half g_wq16[Dd * Dd];
__device__ __half g_wv16[Dd * Dd];
__device__ __half g_wf16[Dd * Dd];
__device__ __half g_qh[BL * Dd];     // (B,H,L,64) head layout, pre-scaled 1/TEMP
__device__ __half g_kh[BL * Dd];
__device__ __half g_vh[BL * Dd];
__device__ unsigned char g_mask8[(size_t)Bb * Ll * Ll];  // 16.78 MB
__device__ __half g_p[(size_t)BH * Ll * Ll];   // unnormalized exp scores fp16
__device__ float  g_rowsum_part[32 * 32 * Ll]; // [bh][seg(ktile*2+wn)][q], 8MB
__device__ __half g_xin[BL * Dd];    // FC input (already permuted), fp16
__device__ float  g_x2[BL * Dd];     // FC output fp32

// ------------------------- mma / ldmatrix / cp.async helpers ----------------
DEV uint32_t sptr(const void* p) { return (uint32_t)__cvta_generic_to_shared(p); }

DEV void ldm_x4(uint32_t r[4], uint32_t addr) {
    asm volatile("ldmatrix.sync.aligned.m8n8.x4.shared.b16 {%0,%1,%2,%3},[%4];"
                 : "=r"(r[0]), "=r"(r[1]), "=r"(r[2]), "=r"(r[3]) : "r"(addr));
}
DEV void ldm_x4_t(uint32_t r[4], uint32_t addr) {
    asm volatile("ldmatrix.sync.aligned.m8n8.x4.trans.shared.b16 {%0,%1,%2,%3},[%4];"
                 : "=r"(r[0]), "=r"(r[1]), "=r"(r[2]), "=r"(r[3]) : "r"(addr));
}
DEV void mma16816(float c[4], const uint32_t a[4], uint32_t b0, uint32_t b1) {
    asm volatile(
        "mma.sync.aligned.m16n8k16.row.col.f32.f16.f16.f32 "
        "{%0,%1,%2,%3},{%4,%5,%6,%7},{%8,%9},{%0,%1,%2,%3};"
        : "+f"(c[0]), "+f"(c[1]), "+f"(c[2]), "+f"(c[3])
        : "r"(a[0]), "r"(a[1]), "r"(a[2]), "r"(a[3]), "r"(b0), "r"(b1));
}
DEV void cpa16(void* dst_smem, const void* src) {
    asm volatile("cp.async.cg.shared.global [%0],[%1],16;"
                 :: "r"(sptr(dst_smem)), "l"(src));
}
DEV void cpa_commit() { asm volatile("cp.async.commit_group;"); }
template <int N> DEV void cpa_wait() { asm volatile("cp.async.wait_group %0;" :: "n"(N)); }

// head layout index for (row r in [0,8192), col c in [0,512))
DEV size_t head_idx(int r, int c) {
    int b = r >> 11, l = r & 2047, h = c >> 6, d = c & 63;
    return ((size_t)((b << 3) | h) * 2048 + l) * 64 + d;
}

// ------------------------- small utility kernels ----------------------------
__global__ void mask8_kernel(const int* __restrict__ in, unsigned char* __restrict__ out, int n) {
    int i = (blockIdx.x * blockDim.x + threadIdx.x) * 4;
    if (i < n) {
        int4 m = *(const int4*)(in + i);
        uchar4 o;
        o.x = (unsigned char)m.x; o.y = (unsigned char)m.y;
        o.z = (unsigned char)m.z; o.w = (unsigned char)m.w;
        *(uchar4*)(out + i) = o;
    }
}
__global__ void w2h_kernel(const float* __restrict__ in, __half* __restrict__ out, int n) {
    int i = (blockIdx.x * blockDim.x + threadIdx.x) * 4;
    if (i < n) {
        float4 v = *(const float4*)(in + i);
        *(__half2*)(out + i)     = __floats2half2_rn(v.x, v.y);
        *(__half2*)(out + i + 2) = __floats2half2_rn(v.z, v.w);
    }
}

// ------------------------- generic GEMM: C = A(M,K) @ W(N,K)^T --------------
// A: fp16 if AHALF else fp32 (register-staged, converted at sts time).
// W: fp16, streamed via cp.async double buffer.
// EPI 0: out = half, head layout, (acc+bias)*scale ; EPI 1: float row-major
template <int EPI, int AHALF>
__global__ __launch_bounds__(256, 2)
void gemm_kernel(const void* __restrict__ Ain, const __half* __restrict__ Wh,
                 const float* __restrict__ bias, void* __restrict__ out,
                 int K, int N, float scale)
{
    constexpr int BM = 128, BN = 128, BK = 32;
    constexpr int AS = 40, BS = 40;
    __shared__ __half As[2][BM * AS];
    __shared__ __half Bs[2][BN * BS];

    int tid = threadIdx.x;
    int warp = tid >> 5, lane = tid & 31;
    int wm = warp >> 1, wn = warp & 1;
    int m0 = blockIdx.y * BM, n0 = blockIdx.x * BN;
    int nk = K / BK;   // 16

    int rA[2], sA[2];
#pragma unroll
    for (int i = 0; i < 2; i++) {
        int u = tid + i * 256;
        rA[i] = u >> 2; sA[i] = (u & 3) * 8;
    }

    float c[2][8][4];
#pragma unroll
    for (int i = 0; i < 2; i++)
#pragma unroll
        for (int j = 0; j < 8; j++)
#pragma unroll
            for (int k = 0; k < 4; k++) c[i][j][k] = 0.0f;

    float4 arf[4];
    int4   arh[2];

    auto ldgA = [&](int kt) {
        int k0 = kt * BK;
        if (AHALF) {
            const __half* Ah = (const __half*)Ain;
#pragma unroll
            for (int i = 0; i < 2; i++)
                arh[i] = *(const int4*)&Ah[(size_t)(m0 + rA[i]) * K + k0 + sA[i]];
        } else {
            const float* Af = (const float*)Ain;
#pragma unroll
            for (int i = 0; i < 2; i++) {
                arf[2 * i]     = *(const float4*)&Af[(size_t)(m0 + rA[i]) * K + k0 + sA[i]];
                arf[2 * i + 1] = *(const float4*)&Af[(size_t)(m0 + rA[i]) * K + k0 + sA[i] + 4];
            }
        }
    };
    auto stsA = [&](int buf) {
#pragma unroll
        for (int i = 0; i < 2; i++) {
            if (AHALF) {
                *(int4*)&As[buf][rA[i] * AS + sA[i]] = arh[i];
            } else {
                __half2 h[4];
                h[0] = __floats2half2_rn(arf[2 * i].x, arf[2 * i].y);
                h[1] = __floats2half2_rn(arf[2 * i].z, arf[2 * i].w);
                h[2] = __floats2half2_rn(arf[2 * i + 1].x, arf[2 * i + 1].y);
                h[3] = __floats2half2_rn(arf[2 * i + 1].z, arf[2 * i + 1].w);
                *(int4*)&As[buf][rA[i] * AS + sA[i]] = *(int4*)h;
            }
        }
    };
    auto cpaW = [&](int kt, int buf) {
        int k0 = kt * BK;
#pragma unroll
        for (int i = 0; i < 2; i++)
            cpa16(&Bs[buf][rA[i] * BS + sA[i]], &Wh[(size_t)(n0 + rA[i]) * K + k0 + sA[i]]);
        cpa_commit();
    };

    cpaW(0, 0);
    ldgA(0);
    stsA(0);
    if (nk > 1) ldgA(1);
    cpa_wait<0>();

    for (int it = 0; it < nk; it++) {
        int buf = it & 1;
        __syncthreads();
        if (it + 1 < nk) {
            cpaW(it + 1, buf ^ 1);
            stsA(buf ^ 1);
            if (it + 2 < nk) ldgA(it + 2);
        }
#pragma unroll
        for (int ks = 0; ks < 2; ks++) {
            uint32_t a[2][4];
#pragma unroll
            for (int mi = 0; mi < 2; mi++) {
                int row = wm * 32 + mi * 16 + (lane & 15);
                int col = ks * 16 + ((lane >> 4) << 3);
                ldm_x4(a[mi], sptr(&As[buf][row * AS + col]));
            }
            uint32_t bb[4][4];
#pragma unroll
            for (int p = 0; p < 4; p++) {
                int tg = lane >> 3, idx = lane & 7;
                int row = wn * 64 + p * 16 + ((tg >> 1) << 3) + idx;
                int col = ks * 16 + ((tg & 1) << 3);
                ldm_x4(bb[p], sptr(&Bs[buf][row * BS + col]));
            }
#pragma unroll
            for (int mi = 0; mi < 2; mi++)
#pragma unroll
                for (int p = 0; p < 4; p++) {
                    mma16816(c[mi][2 * p],     a[mi], bb[p][0], bb[p][1]);
                    mma16816(c[mi][2 * p + 1], a[mi], bb[p][2], bb[p][3]);
                }
        }
        if (it + 1 < nk) cpa_wait<0>();
    }

    int grp = lane >> 2, tig = lane & 3;
#pragma unroll
    for (int mi = 0; mi < 2; mi++)
#pragma unroll
        for (int ni = 0; ni < 8; ni++) {
            int rr = m0 + wm * 32 + mi * 16 + grp;
            int cC = n0 + wn * 64 + ni * 8 + tig * 2;
            float b0 = bias[cC], b1 = bias[cC + 1];
#pragma unroll
            for (int ro = 0; ro < 2; ro++) {
                int r2 = rr + ro * 8;
                float v0 = c[mi][ni][ro * 2 + 0] + b0;
                float v1 = c[mi][ni][ro * 2 + 1] + b1;
                if (EPI == 0) {
                    v0 *= scale; v1 *= scale;
                    *(__half2*)&((__half*)out)[head_idx(r2, cC)] = __floats2half2_rn(v0, v1);
                } else {
                    *(float2*)&((float*)out)[(size_t)r2 * N + cC] = make_float2(v0, v1);
                }
            }
        }
}

// ------------------------- scores: one-shot QK^T + exp + P ------------------
// grid (16 ktile, 16 qtile, 32 bh); tile 128x128, K=64 (no k-loop).
// Writes per-segment partial rowsums (seg = ktile*2 + wn), no atomics.
__global__ __launch_bounds__(256, 2)
void scores_kernel(const __half* __restrict__ qh, const __half* __restrict__ kh,
                   const unsigned char* __restrict__ mask8, __half* __restrict__ P,
                   float* __restrict__ rowsum_part)
{
    __shared__ __half SM[2 * 128 * 72];          // As | Bs, reused for staging
    __half* As = SM;
    __half* Bs = SM + 128 * 72;

    int bh = blockIdx.z;
    int n0 = blockIdx.x * 128;    // k-tile
    int m0 = blockIdx.y * 128;    // q-tile
    const __half* Q = qh + (size_t)bh * Ll * 64;
    const __half* K = kh + (size_t)bh * Ll * 64;
    int b = bh >> 3;

    int tid = threadIdx.x, warp = tid >> 5, lane = tid & 31;
    int wm = warp >> 1, wn = warp & 1;
    int grp = lane >> 2, tig = lane & 3;
    int tg = lane >> 3, idx = lane & 7;

#pragma unroll
    for (int i = 0; i < 4; i++) {
        int u = tid + i * 256; int r = u >> 3, s = u & 7;
        *(int4*)&As[r * 72 + s * 8] = *(const int4*)&Q[(size_t)(m0 + r) * 64 + s * 8];
        *(int4*)&Bs[r * 72 + s * 8] = *(const int4*)&K[(size_t)(n0 + r) * 64 + s * 8];
    }
    __syncthreads();

    float c[2][8][4];
#pragma unroll
    for (int i = 0; i < 2; i++)
#pragma unroll
        for (int j = 0; j < 8; j++)
#pragma unroll
            for (int k = 0; k < 4; k++) c[i][j][k] = 0.0f;

#pragma unroll
    for (int ks = 0; ks < 4; ks++) {
        uint32_t a[2][4];
#pragma unroll
        for (int mi = 0; mi < 2; mi++) {
            int row = wm * 32 + mi * 16 + (lane & 15);
            int col = ks * 16 + ((lane >> 4) << 3);
            ldm_x4(a[mi], sptr(&As[row * 72 + col]));
        }
        uint32_t bb[4][4];
#pragma unroll
        for (int p = 0; p < 4; p++) {
            int row = wn * 64 + p * 16 + ((tg >> 1) << 3) + idx;
            int col = ks * 16 + ((tg & 1) << 3);
            ldm_x4(bb[p], sptr(&Bs[row * 72 + col]));
        }
#pragma unroll
        for (int mi = 0; mi < 2; mi++)
#pragma unroll
            for (int p = 0; p < 4; p++) {
                mma16816(c[mi][2 * p],     a[mi], bb[p][0], bb[p][1]);
                mma16816(c[mi][2 * p + 1], a[mi], bb[p][2], bb[p][3]);
            }
    }
    __syncthreads();   // As/Bs consumed; reuse SM for staging (stride 136)

    int seg = blockIdx.x * 2 + wn;   // rowsum segment
    // exp + mask -> stage into SM (row-major 128x128, stride 136) + partials
#pragma unroll
    for (int mi = 0; mi < 2; mi++)
#pragma unroll
        for (int ro = 0; ro < 2; ro++) {
            int ql = wm * 32 + mi * 16 + ro * 8 + grp;
            int q = m0 + ql;
            size_t mrow = ((size_t)b * Ll + q) * Ll + n0;
            float acc = 0.0f;
#pragma unroll
            for (int ni = 0; ni < 8; ni++) {
                int kk = wn * 64 + ni * 8 + tig * 2;
                uchar2 mm = *(const uchar2*)&mask8[mrow + kk];
                float p0 = mm.x ? 0.0f : __expf(c[mi][ni][ro * 2 + 0]);
                float p1 = mm.y ? 0.0f : __expf(c[mi][ni][ro * 2 + 1]);
                *(__half2*)&SM[ql * 136 + kk] = __floats2half2_rn(p0, p1);
                acc += p0 + p1;
            }
            acc += __shfl_xor_sync(0xffffffffu, acc, 1);
            acc += __shfl_xor_sync(0xffffffffu, acc, 2);
            if (tig == 0) rowsum_part[((size_t)bh * 32 + seg) * Ll + q] = acc;
        }
    __syncthreads();

    // coalesced streaming stores of the P tile
#pragma unroll
    for (int i = 0; i < 8; i++) {
        int u = tid + i * 256;
        int r = u >> 4, s = u & 15;
        int4 val = *(int4*)&SM[r * 136 + s * 8];
        __stcs((int4*)&P[((size_t)bh * Ll + m0 + r) * Ll + n0 + s * 8], val);
    }
}

// ------------------------- pv: attn out + O (3-stage, 1 sync/iter) ----------
// grid (32 qtile, 32 bh); q-tile 64 rows, BK=64, 32 iterations, 3 buffers.
__global__ __launch_bounds__(256)
void pv_kernel(const __half* __restrict__ P, const __half* __restrict__ vh,
               const float* __restrict__ rowsum_part, float* __restrict__ attn_out,
               __half* __restrict__ xin)
{
    extern __shared__ __half sm3[];
    __half* Ps[3] = {sm3,            sm3 + 4608,     sm3 + 2 * 4608};
    __half* Vs[3] = {sm3 + 3 * 4608, sm3 + 4 * 4608, sm3 + 5 * 4608};
    __shared__ float invs_s[64];

    int bh = blockIdx.y;
    int m0 = blockIdx.x * 64;
    const __half* Pg = P + (size_t)bh * Ll * Ll;
    const __half* V  = vh + (size_t)bh * Ll * 64;
    float* aout = attn_out + (size_t)bh * Ll * Ll;

    int tid = threadIdx.x, warp = tid >> 5, lane = tid & 31;
    int wm = warp >> 2, wn = warp & 3;          // 2 x 4 warps, warp tile 32x16
    int grp = lane >> 2, tig = lane & 3;
    int tg = lane >> 3, idx = lane & 7;

    auto issue = [&](int it, int buf) {
        int k0 = it * 64;
#pragma unroll
        for (int i = 0; i < 2; i++) {
            int u = tid + i * 256; int r = u >> 3, s = u & 7;
            cpa16(&Ps[buf][r * 72 + s * 8], &Pg[((size_t)(m0 + r)) * Ll + k0 + s * 8]);
            cpa16(&Vs[buf][r * 72 + s * 8], &V[(size_t)(k0 + r) * 64 + s * 8]);
        }
        cpa_commit();
    };

    issue(0, 0);
    issue(1, 1);

    // build 1/rowsum for this CTA's 64 rows from the 32 partial segments
    if (tid < 64) {
        float s = 0.0f;
        const float* rp = rowsum_part + (size_t)bh * 32 * Ll + m0 + tid;
#pragma unroll
        for (int sg = 0; sg < 32; sg++) s += rp[(size_t)sg * Ll];
        invs_s[tid] = 1.0f / s;
    }
    __syncthreads();

    // attn-epilogue mapping: thread owns row er, cols ec..ec+15 of each tile
    int er = tid >> 2;
    int ec = (tid & 3) * 16;
    float invT = invs_s[er];

    float o[2][2][4];
#pragma unroll
    for (int i = 0; i < 2; i++)
#pragma unroll
        for (int j = 0; j < 2; j++)
#pragma unroll
            for (int k = 0; k < 4; k++) o[i][j][k] = 0.0f;

    for (int it = 0; it < 32; it++) {
        int buf = it % 3;
        cpa_wait<1>();     // tile `it` complete (only it+1's group may remain)
        __syncthreads();   // joins: data visible + all warps done with it-1
        // safe now: buffer (it+2)%3 == (it-1)%3, released by the barrier above
        if (it + 2 < 32) issue(it + 2, (it + 2) % 3);

        // decoupled attn store epilogue (coalesced, streaming)
        {
            int k0 = it * 64;
            int4 r0 = *(int4*)&Ps[buf][er * 72 + ec];
            int4 r1 = *(int4*)&Ps[buf][er * 72 + ec + 8];
            __half2* h0 = (__half2*)&r0;
            __half2* h1 = (__half2*)&r1;
            float* dst = &aout[(size_t)(m0 + er) * Ll + k0 + ec];
            float4 f;
#pragma unroll
            for (int j = 0; j < 2; j++) {
                float2 a0 = __half22float2(h0[2 * j + 0]);
                float2 a1 = __half22float2(h0[2 * j + 1]);
                f = make_float4(a0.x * invT, a0.y * invT, a1.x * invT, a1.y * invT);
                __stcs((float4*)(dst + 4 * j), f);
                float2 b0 = __half22float2(h1[2 * j + 0]);
                float2 b1 = __half22float2(h1[2 * j + 1]);
                f = make_float4(b0.x * invT, b0.y * invT, b1.x * invT, b1.y * invT);
                __stcs((float4*)(dst + 8 + 4 * j), f);
            }
        }

        // O += P_unnorm @ V
#pragma unroll
        for (int ks = 0; ks < 4; ks++) {
            uint32_t a[2][4];
#pragma unroll
            for (int mi = 0; mi < 2; mi++) {
                int row = wm * 32 + mi * 16 + (lane & 15);
                int col = ks * 16 + ((lane >> 4) << 3);
                ldm_x4(a[mi], sptr(&Ps[buf][row * 72 + col]));
            }
            uint32_t bb[4];
            {
                int krow = ks * 16 + ((tg & 1) << 3) + idx;
                int col = wn * 16 + ((tg >> 1) << 3);
                ldm_x4_t(bb, sptr(&Vs[buf][krow * 72 + col]));
            }
#pragma unroll
            for (int mi = 0; mi < 2; mi++) {
                mma16816(o[mi][0], a[mi], bb[0], bb[1]);
                mma16816(o[mi][1], a[mi], bb[2], bb[3]);
            }
        }
    }

    // scale O by 1/rowsum, write xin with the reference's permute index
    int hp = bh >> 2, bp = bh & 3;
#pragma unroll
    for (int mi = 0; mi < 2; mi++) {
#pragma unroll
        for (int ro = 0; ro < 2; ro++) {
            int ql = wm * 32 + mi * 16 + ro * 8 + grp;
            int l = m0 + ql;
            float inv = invs_s[ql];
            size_t n = (size_t)hp * 8192 + (size_t)l * 4 + bp;
#pragma unroll
            for (int ni = 0; ni < 2; ni++) {
                int cC = wn * 16 + ni * 8 + tig * 2;
                *(__half2*)&xin[n * 64 + cC] =
                    __floats2half2_rn(o[mi][ni][ro * 2] * inv, o[mi][ni][ro * 2 + 1] * inv);
            }
        }
    }
}

// ------------------------- layernorm (+ residual) ---------------------------
__global__ __launch_bounds__(128)
void ln_kernel(const float* __restrict__ x2, const float* __restrict__ resid,
               const float* __restrict__ g, const float* __restrict__ bta,
               float* __restrict__ y)
{
    int r = blockIdx.x;
    const float* xr = x2 + (size_t)r * Dd;
    const float* qr = resid + (size_t)r * Dd;
    int t = threadIdx.x;
    float v[4];
    float s = 0.0f, s2 = 0.0f;
#pragma unroll
    for (int i = 0; i < 4; i++) {
        int cI = t + i * 128;
        v[i] = xr[cI] + qr[cI];
        s += v[i]; s2 += v[i] * v[i];
    }
#pragma unroll
    for (int off = 16; off > 0; off >>= 1) {
        s  += __shfl_xor_sync(0xffffffffu, s,  off);
        s2 += __shfl_xor_sync(0xffffffffu, s2, off);
    }
    __shared__ float ss[4], ss2[4];
    int w = t >> 5, lane = t & 31;
    if (lane == 0) { ss[w] = s; ss2[w] = s2; }
    __syncthreads();
    float S = ss[0] + ss[1] + ss[2] + ss[3];
    float S2 = ss2[0] + ss2[1] + ss2[2] + ss2[3];
    float mu = S / Dd;
    float var = S2 / Dd - mu * mu;
    float rstd = rsqrtf(var + LN_EPS);
#pragma unroll
    for (int i = 0; i < 4; i++) {
        int cI = t + i * 128;
        y[(size_t)r * Dd + cI] = (v[i] - mu) * rstd * g[cI] + bta[cI];
    }
}

// ------------------------- host launcher ------------------------------------
extern "C" void kernel_launch(void* const* d_in, const int* in_sizes, int n_in,
                              void* d_out, int out_size)
{
    (void)in_sizes; (void)n_in; (void)out_size;
    const float* q    = (const float*)d_in[0];
    const float* k    = (const float*)d_in[1];
    const float* v    = (const float*)d_in[2];
    const int*   mask = (const int*)d_in[3];
    const float* wq_w = (const float*)d_in[4];
    const float* wq_b = (const float*)d_in[5];
    const float* wv_w = (const float*)d_in[6];
    const float* wv_b = (const float*)d_in[7];
    const float* fc_w = (const float*)d_in[8];
    const float* fc_b = (const float*)d_in[9];
    const float* ln_g = (const float*)d_in[10];
    const float* ln_b = (const float*)d_in[11];

    float* y_out    = (float*)d_out;
    float* attn_out = y_out + (size_t)BL * Dd;

    __half *wq16, *wv16, *wf16, *qh, *kh, *vh, *P, *xin;
    unsigned char* mask8;
    float *rsp, *x2;
    cudaGetSymbolAddress((void**)&wq16, g_wq16);
    cudaGetSymbolAddress((void**)&wv16, g_wv16);
    cudaGetSymbolAddress((void**)&wf16, g_wf16);
    cudaGetSymbolAddress((void**)&qh,   g_qh);
    cudaGetSymbolAddress((void**)&kh,   g_kh);
    cudaGetSymbolAddress((void**)&vh,   g_vh);
    cudaGetSymbolAddress((void**)&mask8, g_mask8);
    cudaGetSymbolAddress((void**)&P,    g_p);
    cudaGetSymbolAddress((void**)&rsp,  g_rowsum_part);
    cudaGetSymbolAddress((void**)&xin,  g_xin);
    cudaGetSymbolAddress((void**)&x2,   g_x2);

    // one-time resources (host-side objects only; identical work every call)
    static cudaStream_t s1, s2, s3;
    static cudaEvent_t e0, e1, e2, e3;
    static bool inited = false;
    if (!inited) {
        cudaStreamCreateWithFlags(&s1, cudaStreamNonBlocking);
        cudaStreamCreateWithFlags(&s2, cudaStreamNonBlocking);
        cudaStreamCreateWithFlags(&s3, cudaStreamNonBlocking);
        cudaEventCreateWithFlags(&e0, cudaEventDisableTiming);
        cudaEventCreateWithFlags(&e1, cudaEventDisableTiming);
        cudaEventCreateWithFlags(&e2, cudaEventDisableTiming);
        cudaEventCreateWithFlags(&e3, cudaEventDisableTiming);
        const int pvSmemInit = 6 * 4608 * 2;   // 55296 bytes
        cudaFuncSetAttribute(pv_kernel, cudaFuncAttributeMaxDynamicSharedMemorySize, pvSmemInit);
        inited = true;
    }
    const int pvSmem = 6 * 4608 * 2;

    const int nM = Bb * Ll * Ll;     // 16777216
    const int nW = Dd * Dd;          // 262144
    dim3 gP(Dd / 128, BL / 128);     // (4, 64)

    // w2h for projection weights first (needed by all three proj GEMMs)
    w2h_kernel<<<nW / 4 / 256, 256, 0, 0>>>(wq_w, wq16, nW);
    w2h_kernel<<<nW / 4 / 256, 256, 0, 0>>>(wv_w, wv16, nW);

    // fork: main(0)=qh, s1=kh, s2=vh, s3=w2h(fc)+mask8
    cudaEventRecord(e0, 0);
    cudaStreamWaitEvent(s1, e0, 0);
    cudaStreamWaitEvent(s2, e0, 0);
    cudaStreamWaitEvent(s3, e0, 0);

    gemm_kernel<0, 0><<<gP, 256, 0, 0>>>(q, wq16, wq_b, qh, Dd, Dd, INV_TEMP);
    gemm_kernel<0, 0><<<gP, 256, 0, s1>>>(k, wq16, wq_b, kh, Dd, Dd, 1.0f);  // k uses wq (bug preserved)
    cudaEventRecord(e1, s1);
    gemm_kernel<0, 0><<<gP, 256, 0, s2>>>(v, wv16, wv_b, vh, Dd, Dd, 1.0f);
    cudaEventRecord(e2, s2);
    w2h_kernel<<<nW / 4 / 256, 256, 0, s3>>>(fc_w, wf16, nW);
    mask8_kernel<<<nM / 4 / 256, 256, 0, s3>>>(mask, mask8, nM);
    cudaEventRecord(e3, s3);

    // join for scores: needs qh (main), kh, mask8
    cudaStreamWaitEvent(0, e1, 0);
    cudaStreamWaitEvent(0, e3, 0);
    scores_kernel<<<dim3(16, 16, 32), 256, 0, 0>>>(qh, kh, mask8, P, rsp);

    // join vh before pv
    cudaStreamWaitEvent(0, e2, 0);
    pv_kernel<<<dim3(32, 32), 256, pvSmem, 0>>>(P, vh, rsp, attn_out, xin);

    gemm_kernel<1, 1><<<gP, 256, 0, 0>>>(xin, wf16, fc_b, x2, Dd, Dd, 1.0f);
    ln_kernel<<<BL, 128, 0, 0>>>(x2, q, ln_g, ln_b, y_out);
}

// round 14
// speedup vs baseline: 1.0344x; 1.0344x over previous
#include <cuda_runtime.h>
#include <cuda_fp16.h>
#include <cstdint>

// ---------------------------------------------------------------------------
// MultiHeadAttention: B=4, L=2048, D=512, H=8, DK=DV=64
// R11 = R8 (best: 486.2us) +
//   P stores use DEFAULT policy (L2 residency; was .cs evict-first)
//   pv traverses (bh, qtile) in REVERSE write order -> newest P read first
//   (attn output stores keep .cs: never re-read)
// ---------------------------------------------------------------------------

#define DEV static __device__ __forceinline__

constexpr int Bb = 4, Ll = 2048, Dd = 512, Hh = 8;
constexpr int BL = Bb * Ll;   // 8192
constexpr int BH = Bb * Hh;   // 32
constexpr float INV_TEMP = 0.125f;   // 1/sqrt(64)
constexpr float LN_EPS = 1e-5f;

// ------------------------- scratch (static device mem) ---------------------
__device__ __half g_wq16[Dd * Dd];
__device__ __half g_wv16[Dd * Dd];
__device__ __half g_wf16[Dd * Dd];
__device__ __half g_qh[BL * Dd];     // (B,H,L,64) head layout, pre-scaled 1/TEMP
__device__ __half g_kh[BL * Dd];
__device__ __half g_vh[BL * Dd];
__device__ unsigned char g_mask8[(size_t)Bb * Ll * Ll];  // 16.78 MB
__device__ __half g_p[(size_t)BH * Ll * Ll];   // unnormalized exp scores fp16
__device__ float  g_rowsum_part[32 * 32 * Ll]; // [bh][seg(ktile*2+wn)][q], 8MB
__device__ __half g_xin[BL * Dd];    // FC input (already permuted), fp16
__device__ float  g_x2[BL * Dd];     // FC output fp32

// ------------------------- mma / ldmatrix / cp.async helpers ----------------
DEV uint32_t sptr(const void* p) { return (uint32_t)__cvta_generic_to_shared(p); }

DEV void ldm_x4(uint32_t r[4], uint32_t addr) {
    asm volatile("ldmatrix.sync.aligned.m8n8.x4.shared.b16 {%0,%1,%2,%3},[%4];"
                 : "=r"(r[0]), "=r"(r[1]), "=r"(r[2]), "=r"(r[3]) : "r"(addr));
}
DEV void ldm_x4_t(uint32_t r[4], uint32_t addr) {
    asm volatile("ldmatrix.sync.aligned.m8n8.x4.trans.shared.b16 {%0,%1,%2,%3},[%4];"
                 : "=r"(r[0]), "=r"(r[1]), "=r"(r[2]), "=r"(r[3]) : "r"(addr));
}
DEV void mma16816(float c[4], const uint32_t a[4], uint32_t b0, uint32_t b1) {
    asm volatile(
        "mma.sync.aligned.m16n8k16.row.col.f32.f16.f16.f32 "
        "{%0,%1,%2,%3},{%4,%5,%6,%7},{%8,%9},{%0,%1,%2,%3};"
        : "+f"(c[0]), "+f"(c[1]), "+f"(c[2]), "+f"(c[3])
        : "r"(a[0]), "r"(a[1]), "r"(a[2]), "r"(a[3]), "r"(b0), "r"(b1));
}
DEV void cpa16(void* dst_smem, const void* src) {
    asm volatile("cp.async.cg.shared.global [%0],[%1],16;"
                 :: "r"(sptr(dst_smem)), "l"(src));
}
DEV void cpa_commit() { asm volatile("cp.async.commit_group;"); }
template <int N> DEV void cpa_wait() { asm volatile("cp.async.wait_group %0;" :: "n"(N)); }

// head layout index for (row r in [0,8192), col c in [0,512))
DEV size_t head_idx(int r, int c) {
    int b = r >> 11, l = r & 2047, h = c >> 6, d = c & 63;
    return ((size_t)((b << 3) | h) * 2048 + l) * 64 + d;
}

// ------------------------- small utility kernels ----------------------------
__global__ void mask8_kernel(const int* __restrict__ in, unsigned char* __restrict__ out, int n) {
    int i = (blockIdx.x * blockDim.x + threadIdx.x) * 4;
    if (i < n) {
        int4 m = *(const int4*)(in + i);
        uchar4 o;
        o.x = (unsigned char)m.x; o.y = (unsigned char)m.y;
        o.z = (unsigned char)m.z; o.w = (unsigned char)m.w;
        *(uchar4*)(out + i) = o;
    }
}
__global__ void w2h_kernel(const float* __restrict__ in, __half* __restrict__ out, int n) {
    int i = (blockIdx.x * blockDim.x + threadIdx.x) * 4;
    if (i < n) {
        float4 v = *(const float4*)(in + i);
        *(__half2*)(out + i)     = __floats2half2_rn(v.x, v.y);
        *(__half2*)(out + i + 2) = __floats2half2_rn(v.z, v.w);
    }
}

// ------------------------- generic GEMM: C = A(M,K) @ W(N,K)^T --------------
// A: fp16 if AHALF else fp32 (register-staged, converted at sts time).
// W: fp16, streamed via cp.async double buffer.
// EPI 0: out = half, head layout, (acc+bias)*scale ; EPI 1: float row-major
template <int EPI, int AHALF>
__global__ __launch_bounds__(256, 2)
void gemm_kernel(const void* __restrict__ Ain, const __half* __restrict__ Wh,
                 const float* __restrict__ bias, void* __restrict__ out,
                 int K, int N, float scale)
{
    constexpr int BM = 128, BN = 128, BK = 32;
    constexpr int AS = 40, BS = 40;
    __shared__ __half As[2][BM * AS];
    __shared__ __half Bs[2][BN * BS];

    int tid = threadIdx.x;
    int warp = tid >> 5, lane = tid & 31;
    int wm = warp >> 1, wn = warp & 1;
    int m0 = blockIdx.y * BM, n0 = blockIdx.x * BN;
    int nk = K / BK;   // 16

    int rA[2], sA[2];
#pragma unroll
    for (int i = 0; i < 2; i++) {
        int u = tid + i * 256;
        rA[i] = u >> 2; sA[i] = (u & 3) * 8;
    }

    float c[2][8][4];
#pragma unroll
    for (int i = 0; i < 2; i++)
#pragma unroll
        for (int j = 0; j < 8; j++)
#pragma unroll
            for (int k = 0; k < 4; k++) c[i][j][k] = 0.0f;

    float4 arf[4];
    int4   arh[2];

    auto ldgA = [&](int kt) {
        int k0 = kt * BK;
        if (AHALF) {
            const __half* Ah = (const __half*)Ain;
#pragma unroll
            for (int i = 0; i < 2; i++)
                arh[i] = *(const int4*)&Ah[(size_t)(m0 + rA[i]) * K + k0 + sA[i]];
        } else {
            const float* Af = (const float*)Ain;
#pragma unroll
            for (int i = 0; i < 2; i++) {
                arf[2 * i]     = *(const float4*)&Af[(size_t)(m0 + rA[i]) * K + k0 + sA[i]];
                arf[2 * i + 1] = *(const float4*)&Af[(size_t)(m0 + rA[i]) * K + k0 + sA[i] + 4];
            }
        }
    };
    auto stsA = [&](int buf) {
#pragma unroll
        for (int i = 0; i < 2; i++) {
            if (AHALF) {
                *(int4*)&As[buf][rA[i] * AS + sA[i]] = arh[i];
            } else {
                __half2 h[4];
                h[0] = __floats2half2_rn(arf[2 * i].x, arf[2 * i].y);
                h[1] = __floats2half2_rn(arf[2 * i].z, arf[2 * i].w);
                h[2] = __floats2half2_rn(arf[2 * i + 1].x, arf[2 * i + 1].y);
                h[3] = __floats2half2_rn(arf[2 * i + 1].z, arf[2 * i + 1].w);
                *(int4*)&As[buf][rA[i] * AS + sA[i]] = *(int4*)h;
            }
        }
    };
    auto cpaW = [&](int kt, int buf) {
        int k0 = kt * BK;
#pragma unroll
        for (int i = 0; i < 2; i++)
            cpa16(&Bs[buf][rA[i] * BS + sA[i]], &Wh[(size_t)(n0 + rA[i]) * K + k0 + sA[i]]);
        cpa_commit();
    };

    cpaW(0, 0);
    ldgA(0);
    stsA(0);
    if (nk > 1) ldgA(1);
    cpa_wait<0>();

    for (int it = 0; it < nk; it++) {
        int buf = it & 1;
        __syncthreads();
        if (it + 1 < nk) {
            cpaW(it + 1, buf ^ 1);
            stsA(buf ^ 1);
            if (it + 2 < nk) ldgA(it + 2);
        }
#pragma unroll
        for (int ks = 0; ks < 2; ks++) {
            uint32_t a[2][4];
#pragma unroll
            for (int mi = 0; mi < 2; mi++) {
                int row = wm * 32 + mi * 16 + (lane & 15);
                int col = ks * 16 + ((lane >> 4) << 3);
                ldm_x4(a[mi], sptr(&As[buf][row * AS + col]));
            }
            uint32_t bb[4][4];
#pragma unroll
            for (int p = 0; p < 4; p++) {
                int tg = lane >> 3, idx = lane & 7;
                int row = wn * 64 + p * 16 + ((tg >> 1) << 3) + idx;
                int col = ks * 16 + ((tg & 1) << 3);
                ldm_x4(bb[p], sptr(&Bs[buf][row * BS + col]));
            }
#pragma unroll
            for (int mi = 0; mi < 2; mi++)
#pragma unroll
                for (int p = 0; p < 4; p++) {
                    mma16816(c[mi][2 * p],     a[mi], bb[p][0], bb[p][1]);
                    mma16816(c[mi][2 * p + 1], a[mi], bb[p][2], bb[p][3]);
                }
        }
        if (it + 1 < nk) cpa_wait<0>();
    }

    int grp = lane >> 2, tig = lane & 3;
#pragma unroll
    for (int mi = 0; mi < 2; mi++)
#pragma unroll
        for (int ni = 0; ni < 8; ni++) {
            int rr = m0 + wm * 32 + mi * 16 + grp;
            int cC = n0 + wn * 64 + ni * 8 + tig * 2;
            float b0 = bias[cC], b1 = bias[cC + 1];
#pragma unroll
            for (int ro = 0; ro < 2; ro++) {
                int r2 = rr + ro * 8;
                float v0 = c[mi][ni][ro * 2 + 0] + b0;
                float v1 = c[mi][ni][ro * 2 + 1] + b1;
                if (EPI == 0) {
                    v0 *= scale; v1 *= scale;
                    *(__half2*)&((__half*)out)[head_idx(r2, cC)] = __floats2half2_rn(v0, v1);
                } else {
                    *(float2*)&((float*)out)[(size_t)r2 * N + cC] = make_float2(v0, v1);
                }
            }
        }
}

// ------------------------- scores: one-shot QK^T + exp + P ------------------
// grid (16 ktile, 16 qtile, 32 bh); tile 128x128, K=64 (no k-loop).
// Writes per-segment partial rowsums (seg = ktile*2 + wn), no atomics.
// P stores use DEFAULT policy -> tail of P stays L2-resident for pv.
__global__ __launch_bounds__(256)
void scores_kernel(const __half* __restrict__ qh, const __half* __restrict__ kh,
                   const unsigned char* __restrict__ mask8, __half* __restrict__ P,
                   float* __restrict__ rowsum_part)
{
    __shared__ __half SM[2 * 128 * 72];          // As | Bs, reused for staging
    __half* As = SM;
    __half* Bs = SM + 128 * 72;

    int bh = blockIdx.z;
    int n0 = blockIdx.x * 128;    // k-tile
    int m0 = blockIdx.y * 128;    // q-tile
    const __half* Q = qh + (size_t)bh * Ll * 64;
    const __half* K = kh + (size_t)bh * Ll * 64;
    int b = bh >> 3;

    int tid = threadIdx.x, warp = tid >> 5, lane = tid & 31;
    int wm = warp >> 1, wn = warp & 1;
    int grp = lane >> 2, tig = lane & 3;
    int tg = lane >> 3, idx = lane & 7;

#pragma unroll
    for (int i = 0; i < 4; i++) {
        int u = tid + i * 256; int r = u >> 3, s = u & 7;
        *(int4*)&As[r * 72 + s * 8] = *(const int4*)&Q[(size_t)(m0 + r) * 64 + s * 8];
        *(int4*)&Bs[r * 72 + s * 8] = *(const int4*)&K[(size_t)(n0 + r) * 64 + s * 8];
    }
    __syncthreads();

    float c[2][8][4];
#pragma unroll
    for (int i = 0; i < 2; i++)
#pragma unroll
        for (int j = 0; j < 8; j++)
#pragma unroll
            for (int k = 0; k < 4; k++) c[i][j][k] = 0.0f;

#pragma unroll
    for (int ks = 0; ks < 4; ks++) {
        uint32_t a[2][4];
#pragma unroll
        for (int mi = 0; mi < 2; mi++) {
            int row = wm * 32 + mi * 16 + (lane & 15);
            int col = ks * 16 + ((lane >> 4) << 3);
            ldm_x4(a[mi], sptr(&As[row * 72 + col]));
        }
        uint32_t bb[4][4];
#pragma unroll
        for (int p = 0; p < 4; p++) {
            int row = wn * 64 + p * 16 + ((tg >> 1) << 3) + idx;
            int col = ks * 16 + ((tg & 1) << 3);
            ldm_x4(bb[p], sptr(&Bs[row * 72 + col]));
        }
#pragma unroll
        for (int mi = 0; mi < 2; mi++)
#pragma unroll
            for (int p = 0; p < 4; p++) {
                mma16816(c[mi][2 * p],     a[mi], bb[p][0], bb[p][1]);
                mma16816(c[mi][2 * p + 1], a[mi], bb[p][2], bb[p][3]);
            }
    }
    __syncthreads();   // As/Bs consumed; reuse SM for staging (stride 136)

    int seg = blockIdx.x * 2 + wn;   // rowsum segment
    // exp + mask -> stage into SM (row-major 128x128, stride 136) + partials
#pragma unroll
    for (int mi = 0; mi < 2; mi++)
#pragma unroll
        for (int ro = 0; ro < 2; ro++) {
            int ql = wm * 32 + mi * 16 + ro * 8 + grp;
            int q = m0 + ql;
            size_t mrow = ((size_t)b * Ll + q) * Ll + n0;
            float acc = 0.0f;
#pragma unroll
            for (int ni = 0; ni < 8; ni++) {
                int kk = wn * 64 + ni * 8 + tig * 2;
                uchar2 mm = *(const uchar2*)&mask8[mrow + kk];
                float p0 = mm.x ? 0.0f : __expf(c[mi][ni][ro * 2 + 0]);
                float p1 = mm.y ? 0.0f : __expf(c[mi][ni][ro * 2 + 1]);
                *(__half2*)&SM[ql * 136 + kk] = __floats2half2_rn(p0, p1);
                acc += p0 + p1;
            }
            acc += __shfl_xor_sync(0xffffffffu, acc, 1);
            acc += __shfl_xor_sync(0xffffffffu, acc, 2);
            if (tig == 0) rowsum_part[((size_t)bh * 32 + seg) * Ll + q] = acc;
        }
    __syncthreads();

    // coalesced stores of the P tile (default policy: want L2 residency)
#pragma unroll
    for (int i = 0; i < 8; i++) {
        int u = tid + i * 256;
        int r = u >> 4, s = u & 15;
        int4 val = *(int4*)&SM[r * 136 + s * 8];
        *(int4*)&P[((size_t)bh * Ll + m0 + r) * Ll + n0 + s * 8] = val;
    }
}

// ------------------------- pv: attn out + O (3-stage cp.async) --------------
// grid (32 qtile, 32 bh) traversed in REVERSE write order; q-tile 64 rows,
// BK=64, 32 iterations, 3 buffers.
__global__ __launch_bounds__(256)
void pv_kernel(const __half* __restrict__ P, const __half* __restrict__ vh,
               const float* __restrict__ rowsum_part, float* __restrict__ attn_out,
               __half* __restrict__ xin)
{
    extern __shared__ __half sm3[];
    __half* Ps[3] = {sm3,            sm3 + 4608,     sm3 + 2 * 4608};
    __half* Vs[3] = {sm3 + 3 * 4608, sm3 + 4 * 4608, sm3 + 5 * 4608};
    __shared__ float invs_s[64];

    int bh = 31 - blockIdx.y;            // reverse: newest-written P first
    int m0 = (31 - blockIdx.x) * 64;
    const __half* Pg = P + (size_t)bh * Ll * Ll;
    const __half* V  = vh + (size_t)bh * Ll * 64;
    float* aout = attn_out + (size_t)bh * Ll * Ll;

    int tid = threadIdx.x, warp = tid >> 5, lane = tid & 31;
    int wm = warp >> 2, wn = warp & 3;          // 2 x 4 warps, warp tile 32x16
    int grp = lane >> 2, tig = lane & 3;
    int tg = lane >> 3, idx = lane & 7;

    auto issue = [&](int it, int buf) {
        int k0 = it * 64;
#pragma unroll
        for (int i = 0; i < 2; i++) {
            int u = tid + i * 256; int r = u >> 3, s = u & 7;
            cpa16(&Ps[buf][r * 72 + s * 8], &Pg[((size_t)(m0 + r)) * Ll + k0 + s * 8]);
            cpa16(&Vs[buf][r * 72 + s * 8], &V[(size_t)(k0 + r) * 64 + s * 8]);
        }
        cpa_commit();
    };

    issue(0, 0);
    issue(1, 1);

    // build 1/rowsum for this CTA's 64 rows from the 32 partial segments
    if (tid < 64) {
        float s = 0.0f;
        const float* rp = rowsum_part + (size_t)bh * 32 * Ll + m0 + tid;
#pragma unroll
        for (int sg = 0; sg < 32; sg++) s += rp[(size_t)sg * Ll];
        invs_s[tid] = 1.0f / s;
    }
    __syncthreads();

    // attn-epilogue mapping: thread owns row er, cols ec..ec+15 of each tile
    int er = tid >> 2;
    int ec = (tid & 3) * 16;
    float invT = invs_s[er];

    float o[2][2][4];
#pragma unroll
    for (int i = 0; i < 2; i++)
#pragma unroll
        for (int j = 0; j < 2; j++)
#pragma unroll
            for (int k = 0; k < 4; k++) o[i][j][k] = 0.0f;

    for (int it = 0; it < 32; it++) {
        int buf = it % 3;
        if (it + 2 < 32) issue(it + 2, (it + 2) % 3);
        cpa_wait<2>();     // tile `it` complete (<=2 groups outstanding)
        __syncthreads();

        // decoupled attn store epilogue (coalesced, streaming)
        {
            int k0 = it * 64;
            int4 r0 = *(int4*)&Ps[buf][er * 72 + ec];
            int4 r1 = *(int4*)&Ps[buf][er * 72 + ec + 8];
            __half2* h0 = (__half2*)&r0;
            __half2* h1 = (__half2*)&r1;
            float* dst = &aout[(size_t)(m0 + er) * Ll + k0 + ec];
            float4 f;
#pragma unroll
            for (int j = 0; j < 2; j++) {
                float2 a0 = __half22float2(h0[2 * j + 0]);
                float2 a1 = __half22float2(h0[2 * j + 1]);
                f = make_float4(a0.x * invT, a0.y * invT, a1.x * invT, a1.y * invT);
                __stcs((float4*)(dst + 4 * j), f);
                float2 b0 = __half22float2(h1[2 * j + 0]);
                float2 b1 = __half22float2(h1[2 * j + 1]);
                f = make_float4(b0.x * invT, b0.y * invT, b1.x * invT, b1.y * invT);
                __stcs((float4*)(dst + 8 + 4 * j), f);
            }
        }

        // O += P_unnorm @ V
#pragma unroll
        for (int ks = 0; ks < 4; ks++) {
            uint32_t a[2][4];
#pragma unroll
            for (int mi = 0; mi < 2; mi++) {
                int row = wm * 32 + mi * 16 + (lane & 15);
                int col = ks * 16 + ((lane >> 4) << 3);
                ldm_x4(a[mi], sptr(&Ps[buf][row * 72 + col]));
            }
            uint32_t bb[4];
            {
                int krow = ks * 16 + ((tg & 1) << 3) + idx;
                int col = wn * 16 + ((tg >> 1) << 3);
                ldm_x4_t(bb, sptr(&Vs[buf][krow * 72 + col]));
            }
#pragma unroll
            for (int mi = 0; mi < 2; mi++) {
                mma16816(o[mi][0], a[mi], bb[0], bb[1]);
                mma16816(o[mi][1], a[mi], bb[2], bb[3]);
            }
        }
        __syncthreads();   // release buf before it is re-issued
    }

    // scale O by 1/rowsum, write xin with the reference's permute index
    int hp = bh >> 2, bp = bh & 3;
#pragma unroll
    for (int mi = 0; mi < 2; mi++) {
#pragma unroll
        for (int ro = 0; ro < 2; ro++) {
            int ql = wm * 32 + mi * 16 + ro * 8 + grp;
            int l = m0 + ql;
            float inv = invs_s[ql];
            size_t n = (size_t)hp * 8192 + (size_t)l * 4 + bp;
#pragma unroll
            for (int ni = 0; ni < 2; ni++) {
                int cC = wn * 16 + ni * 8 + tig * 2;
                *(__half2*)&xin[n * 64 + cC] =
                    __floats2half2_rn(o[mi][ni][ro * 2] * inv, o[mi][ni][ro * 2 + 1] * inv);
            }
        }
    }
}

// ------------------------- layernorm (+ residual) ---------------------------
__global__ __launch_bounds__(128)
void ln_kernel(const float* __restrict__ x2, const float* __restrict__ resid,
               const float* __restrict__ g, const float* __restrict__ bta,
               float* __restrict__ y)
{
    int r = blockIdx.x;
    const float* xr = x2 + (size_t)r * Dd;
    const float* qr = resid + (size_t)r * Dd;
    int t = threadIdx.x;
    float v[4];
    float s = 0.0f, s2 = 0.0f;
#pragma unroll
    for (int i = 0; i < 4; i++) {
        int cI = t + i * 128;
        v[i] = xr[cI] + qr[cI];
        s += v[i]; s2 += v[i] * v[i];
    }
#pragma unroll
    for (int off = 16; off > 0; off >>= 1) {
        s  += __shfl_xor_sync(0xffffffffu, s,  off);
        s2 += __shfl_xor_sync(0xffffffffu, s2, off);
    }
    __shared__ float ss[4], ss2[4];
    int w = t >> 5, lane = t & 31;
    if (lane == 0) { ss[w] = s; ss2[w] = s2; }
    __syncthreads();
    float S = ss[0] + ss[1] + ss[2] + ss[3];
    float S2 = ss2[0] + ss2[1] + ss2[2] + ss2[3];
    float mu = S / Dd;
    float var = S2 / Dd - mu * mu;
    float rstd = rsqrtf(var + LN_EPS);
#pragma unroll
    for (int i = 0; i < 4; i++) {
        int cI = t + i * 128;
        y[(size_t)r * Dd + cI] = (v[i] - mu) * rstd * g[cI] + bta[cI];
    }
}

// ------------------------- host launcher ------------------------------------
extern "C" void kernel_launch(void* const* d_in, const int* in_sizes, int n_in,
                              void* d_out, int out_size)
{
    (void)in_sizes; (void)n_in; (void)out_size;
    const float* q    = (const float*)d_in[0];
    const float* k    = (const float*)d_in[1];
    const float* v    = (const float*)d_in[2];
    const int*   mask = (const int*)d_in[3];
    const float* wq_w = (const float*)d_in[4];
    const float* wq_b = (const float*)d_in[5];
    const float* wv_w = (const float*)d_in[6];
    const float* wv_b = (const float*)d_in[7];
    const float* fc_w = (const float*)d_in[8];
    const float* fc_b = (const float*)d_in[9];
    const float* ln_g = (const float*)d_in[10];
    const float* ln_b = (const float*)d_in[11];

    float* y_out    = (float*)d_out;
    float* attn_out = y_out + (size_t)BL * Dd;

    __half *wq16, *wv16, *wf16, *qh, *kh, *vh, *P, *xin;
    unsigned char* mask8;
    float *rsp, *x2;
    cudaGetSymbolAddress((void**)&wq16, g_wq16);
    cudaGetSymbolAddress((void**)&wv16, g_wv16);
    cudaGetSymbolAddress((void**)&wf16, g_wf16);
    cudaGetSymbolAddress((void**)&qh,   g_qh);
    cudaGetSymbolAddress((void**)&kh,   g_kh);
    cudaGetSymbolAddress((void**)&vh,   g_vh);
    cudaGetSymbolAddress((void**)&mask8, g_mask8);
    cudaGetSymbolAddress((void**)&P,    g_p);
    cudaGetSymbolAddress((void**)&rsp,  g_rowsum_part);
    cudaGetSymbolAddress((void**)&xin,  g_xin);
    cudaGetSymbolAddress((void**)&x2,   g_x2);

    // one-time resources (host-side objects only; identical work every call)
    static cudaStream_t s1, s2, s3;
    static cudaEvent_t e0, e1, e2, e3;
    static bool inited = false;
    if (!inited) {
        cudaStreamCreateWithFlags(&s1, cudaStreamNonBlocking);
        cudaStreamCreateWithFlags(&s2, cudaStreamNonBlocking);
        cudaStreamCreateWithFlags(&s3, cudaStreamNonBlocking);
        cudaEventCreateWithFlags(&e0, cudaEventDisableTiming);
        cudaEventCreateWithFlags(&e1, cudaEventDisableTiming);
        cudaEventCreateWithFlags(&e2, cudaEventDisableTiming);
        cudaEventCreateWithFlags(&e3, cudaEventDisableTiming);
        const int pvSmemInit = 6 * 4608 * 2;   // 55296 bytes
        cudaFuncSetAttribute(pv_kernel, cudaFuncAttributeMaxDynamicSharedMemorySize, pvSmemInit);
        inited = true;
    }
    const int pvSmem = 6 * 4608 * 2;

    const int nM = Bb * Ll * Ll;     // 16777216
    const int nW = Dd * Dd;          // 262144
    dim3 gP(Dd / 128, BL / 128);     // (4, 64)

    // w2h for projection weights first (needed by all three proj GEMMs)
    w2h_kernel<<<nW / 4 / 256, 256, 0, 0>>>(wq_w, wq16, nW);
    w2h_kernel<<<nW / 4 / 256, 256, 0, 0>>>(wv_w, wv16, nW);

    // fork: main(0)=qh, s1=kh, s2=vh, s3=w2h(fc)+mask8
    cudaEventRecord(e0, 0);
    cudaStreamWaitEvent(s1, e0, 0);
    cudaStreamWaitEvent(s2, e0, 0);
    cudaStreamWaitEvent(s3, e0, 0);

    gemm_kernel<0, 0><<<gP, 256, 0, 0>>>(q, wq16, wq_b, qh, Dd, Dd, INV_TEMP);
    gemm_kernel<0, 0><<<gP, 256, 0, s1>>>(k, wq16, wq_b, kh, Dd, Dd, 1.0f);  // k uses wq (bug preserved)
    cudaEventRecord(e1, s1);
    gemm_kernel<0, 0><<<gP, 256, 0, s2>>>(v, wv16, wv_b, vh, Dd, Dd, 1.0f);
    cudaEventRecord(e2, s2);
    w2h_kernel<<<nW / 4 / 256, 256, 0, s3>>>(fc_w, wf16, nW);
    mask8_kernel<<<nM / 4 / 256, 256, 0, s3>>>(mask, mask8, nM);
    cudaEventRecord(e3, s3);

    // join for scores: needs qh (main), kh, mask8
    cudaStreamWaitEvent(0, e1, 0);
    cudaStreamWaitEvent(0, e3, 0);
    scores_kernel<<<dim3(16, 16, 32), 256, 0, 0>>>(qh, kh, mask8, P, rsp);

    // join vh before pv
    cudaStreamWaitEvent(0, e2, 0);
    pv_kernel<<<dim3(32, 32), 256, pvSmem, 0>>>(P, vh, rsp, attn_out, xin);

    gemm_kernel<1, 1><<<gP, 256, 0, 0>>>(xin, wf16, fc_b, x2, Dd, Dd, 1.0f);
    ln_kernel<<<BL, 128, 0, 0>>>(x2, q, ln_g, ln_b, y_out);
}